// round 6
// baseline (speedup 1.0000x reference)
#include <cuda_runtime.h>

// Problem constants: q,k,v [B=4, H=8, N=2048, D=64] fp32, scale scalar.
// out = softmax(logits * softmax(logits/0.5)) @ V, logits = scale * Q K^T.

constexpr int TPB  = 256;
constexpr int MQ   = 16;     // queries per CTA
constexpr int TK   = 256;    // keys per SMEM tile
constexpr int D    = 64;
constexpr int N    = 2048;
constexpr int LSTR = 2052;   // logits row stride in floats (pad 4 for bank spread)
constexpr int NT   = N / TK; // 8 tiles
constexpr int BH   = 32;     // B*H

constexpr int SMEM_FLOATS = MQ * LSTR + D * TK + D * MQ + 32;

// Load a TKxD tile (row-major [k][d] in gmem) into SMEM transposed [d][k],
// XOR-swizzled at float4 granularity so that both row-contiguous reads
// (phase 1) and column-of-float4 reads (phase 3) are near conflict-free.
// Element (d,k) lives at ts[d*TK + 4*((k>>2) ^ ((d>>2)&7)) + (k&3)].
__device__ __forceinline__ void load_tile_T(const float* __restrict__ src,
                                            float* __restrict__ ts, int tid)
{
#pragma unroll
    for (int r = 0; r < 16; r++) {
        int idx = r * 256 + tid;
        int kk  = idx >> 4;          // 0..255
        int d4  = (idx & 15) << 2;   // 0,4,...,60
        float4 v = *reinterpret_cast<const float4*>(src + kk * D + d4);
        int s   = (d4 >> 2) & 7;
        int col = ((((kk >> 2) ^ s) << 2) | (kk & 3));
        ts[(d4 + 0) * TK + col] = v.x;
        ts[(d4 + 1) * TK + col] = v.y;
        ts[(d4 + 2) * TK + col] = v.z;
        ts[(d4 + 3) * TK + col] = v.w;
    }
}

__global__ __launch_bounds__(TPB, 1)
void stk_branch_kernel(const float* __restrict__ Q, const float* __restrict__ K,
                       const float* __restrict__ V, const float* __restrict__ scale_p,
                       float* __restrict__ O)
{
    extern __shared__ float sm[];
    float* logits = sm;                    // MQ * LSTR
    float* ts     = logits + MQ * LSTR;    // D * TK   (K tile / V tile / O partials)
    float* qt     = ts + D * TK;           // D * MQ   (Q transposed)
    float* inv2s  = qt + D * MQ;           // MQ

    const int tid   = threadIdx.x;
    const int bh    = blockIdx.y;
    const int qtile = blockIdx.x;
    const int base  = bh * (N * D);
    const int qbase = qtile * MQ;
    const float sc  = __ldg(scale_p);

    // ---- Load Q tile transposed: qt[d][qi] ----
    {
        int qi = tid >> 4;           // 0..15
        int d4 = (tid & 15) << 2;    // 0..60
        float4 qv = *reinterpret_cast<const float4*>(Q + base + (qbase + qi) * D + d4);
        qt[(d4 + 0) * MQ + qi] = qv.x;
        qt[(d4 + 1) * MQ + qi] = qv.y;
        qt[(d4 + 2) * MQ + qi] = qv.z;
        qt[(d4 + 3) * MQ + qi] = qv.w;
    }

    // ---- Phase 1: logits[q][k] = sc * Q.K^T into SMEM ----
    const int ty = tid >> 6;        // 0..3  -> q block
    const int tx = tid & 63;        // 0..63 -> k block
    const int q0 = ty << 2;
    const int k0 = tx << 2;

    for (int t = 0; t < NT; t++) {
        __syncthreads();                       // WAR on ts (and qt visibility at t=0)
        load_tile_T(K + base + t * TK * D, ts, tid);
        __syncthreads();

        float acc[4][4];
#pragma unroll
        for (int i = 0; i < 4; i++)
#pragma unroll
            for (int j = 0; j < 4; j++) acc[i][j] = 0.f;

#pragma unroll 8
        for (int d = 0; d < D; d++) {
            float4 qv = *reinterpret_cast<const float4*>(&qt[d * MQ + q0]);
            float4 kv = *reinterpret_cast<const float4*>(&ts[d * TK + ((tx ^ ((d >> 2) & 7)) << 2)]);
            float qa[4] = {qv.x, qv.y, qv.z, qv.w};
            float ka[4] = {kv.x, kv.y, kv.z, kv.w};
#pragma unroll
            for (int i = 0; i < 4; i++)
#pragma unroll
                for (int j = 0; j < 4; j++)
                    acc[i][j] = fmaf(qa[i], ka[j], acc[i][j]);
        }

        int kb = t * TK;
#pragma unroll
        for (int i = 0; i < 4; i++) {
            float4 st = make_float4(acc[i][0] * sc, acc[i][1] * sc,
                                    acc[i][2] * sc, acc[i][3] * sc);
            *reinterpret_cast<float4*>(&logits[(q0 + i) * LSTR + kb + k0]) = st;
        }
    }
    __syncthreads();

    // ---- Phase 2: per-row double softmax, in place (warp w owns rows 2w, 2w+1) ----
    {
        const int w = tid >> 5, lane = tid & 31;
#pragma unroll
        for (int rr = 0; rr < 2; rr++) {
            float* L = logits + ((w << 1) + rr) * LSTR;

            // pass 1: row max of logits
            float m = -1e30f;
            for (int it = 0; it < 16; it++) {
                float4 x = *reinterpret_cast<const float4*>(&L[(it * 32 + lane) << 2]);
                m = fmaxf(m, fmaxf(fmaxf(x.x, x.y), fmaxf(x.z, x.w)));
            }
#pragma unroll
            for (int o = 16; o; o >>= 1) m = fmaxf(m, __shfl_xor_sync(0xffffffffu, m, o));

            // pass 2: sum of exp(2*(x-m))  (softmax with T=0.5)
            float s = 0.f;
            for (int it = 0; it < 16; it++) {
                float4 x = *reinterpret_cast<const float4*>(&L[(it * 32 + lane) << 2]);
                s += __expf(2.f * (x.x - m)) + __expf(2.f * (x.y - m))
                   + __expf(2.f * (x.z - m)) + __expf(2.f * (x.w - m));
            }
#pragma unroll
            for (int o = 16; o; o >>= 1) s += __shfl_xor_sync(0xffffffffu, s, o);
            float inv1 = 1.f / s;

            // pass 3: g = x * softmax1(x), overwrite; track max(g)
            float m2 = -1e30f;
            for (int it = 0; it < 16; it++) {
                float4* p4 = reinterpret_cast<float4*>(&L[(it * 32 + lane) << 2]);
                float4 x = *p4;
                x.x = x.x * (__expf(2.f * (x.x - m)) * inv1);
                x.y = x.y * (__expf(2.f * (x.y - m)) * inv1);
                x.z = x.z * (__expf(2.f * (x.z - m)) * inv1);
                x.w = x.w * (__expf(2.f * (x.w - m)) * inv1);
                *p4 = x;
                m2 = fmaxf(m2, fmaxf(fmaxf(x.x, x.y), fmaxf(x.z, x.w)));
            }
#pragma unroll
            for (int o = 16; o; o >>= 1) m2 = fmaxf(m2, __shfl_xor_sync(0xffffffffu, m2, o));

            // pass 4: p = exp(g - m2), overwrite; sum
            float s2 = 0.f;
            for (int it = 0; it < 16; it++) {
                float4* p4 = reinterpret_cast<float4*>(&L[(it * 32 + lane) << 2]);
                float4 x = *p4;
                x.x = __expf(x.x - m2); x.y = __expf(x.y - m2);
                x.z = __expf(x.z - m2); x.w = __expf(x.w - m2);
                *p4 = x;
                s2 += x.x + x.y + x.z + x.w;
            }
#pragma unroll
            for (int o = 16; o; o >>= 1) s2 += __shfl_xor_sync(0xffffffffu, s2, o);
            if (lane == 0) inv2s[(w << 1) + rr] = 1.f / s2;
        }
    }

    // ---- Phase 3: O = P.V, split-K across 4 thread groups ----
    const int g   = tid >> 6;        // 0..3  key-split group
    const int u   = tid & 63;
    const int gy  = u >> 4;          // 0..3  q block
    const int gx  = u & 15;          // 0..15 d block
    const int pq0 = gy << 2;
    const int pd0 = gx << 2;

    float oacc[4][4];
#pragma unroll
    for (int i = 0; i < 4; i++)
#pragma unroll
        for (int j = 0; j < 4; j++) oacc[i][j] = 0.f;

    for (int t = 0; t < NT; t++) {
        __syncthreads();                       // prev compute done with ts (and stats done at t=0)
        load_tile_T(V + base + t * TK * D, ts, tid);
        __syncthreads();

        int kb = t * TK;
#pragma unroll 2
        for (int kq = 0; kq < 16; kq++) {
            int kk = (g << 6) + (kq << 2);
            float4 p[4], vv[4];
#pragma unroll
            for (int i = 0; i < 4; i++)
                p[i] = *reinterpret_cast<const float4*>(&logits[(pq0 + i) * LSTR + kb + kk]);
            int c = (((kk >> 2) ^ (gx & 7)) << 2);
#pragma unroll
            for (int j = 0; j < 4; j++)
                vv[j] = *reinterpret_cast<const float4*>(&ts[(pd0 + j) * TK + c]);
#pragma unroll
            for (int i = 0; i < 4; i++)
#pragma unroll
                for (int j = 0; j < 4; j++) {
                    oacc[i][j] = fmaf(p[i].x, vv[j].x, oacc[i][j]);
                    oacc[i][j] = fmaf(p[i].y, vv[j].y, oacc[i][j]);
                    oacc[i][j] = fmaf(p[i].z, vv[j].z, oacc[i][j]);
                    oacc[i][j] = fmaf(p[i].w, vv[j].w, oacc[i][j]);
                }
        }
    }

    // ---- Reduce split-K partials and write output ----
    __syncthreads();                 // everyone done reading ts as V tile
#pragma unroll
    for (int i = 0; i < 4; i++)
#pragma unroll
        for (int j = 0; j < 4; j++)
            ts[g * (MQ * D) + (pq0 + i) * D + pd0 + j] = oacc[i][j];
    __syncthreads();

    {
        int o4 = tid << 2;                 // 0..1020, covers MQ*D = 1024
        int qq = o4 >> 6;                  // query within tile
        float4 r = make_float4(0.f, 0.f, 0.f, 0.f);
#pragma unroll
        for (int g2 = 0; g2 < 4; g2++) {
            float4 pv = *reinterpret_cast<const float4*>(&ts[g2 * (MQ * D) + o4]);
            r.x += pv.x; r.y += pv.y; r.z += pv.z; r.w += pv.w;
        }
        float iv = inv2s[qq];
        r.x *= iv; r.y *= iv; r.z *= iv; r.w *= iv;
        *reinterpret_cast<float4*>(O + base + (qbase + qq) * D + (o4 & 63)) = r;
    }
}

extern "C" void kernel_launch(void* const* d_in, const int* in_sizes, int n_in,
                              void* d_out, int out_size)
{
    const float* q  = (const float*)d_in[0];
    const float* k  = (const float*)d_in[1];
    const float* v  = (const float*)d_in[2];
    const float* sc = (const float*)d_in[3];
    float* o = (float*)d_out;

    size_t smem = SMEM_FLOATS * sizeof(float);
    cudaFuncSetAttribute(stk_branch_kernel,
                         cudaFuncAttributeMaxDynamicSharedMemorySize, (int)smem);
    dim3 grid(N / MQ, BH);
    stk_branch_kernel<<<grid, TPB, smem>>>(q, k, v, sc, o);
}

// round 12
// speedup vs baseline: 1.7621x; 1.7621x over previous
#include <cuda_runtime.h>
#include <cstdint>

// out = softmax(logits * softmax(logits/0.5)) @ V, logits = scale * Q K^T
// q,k,v: [B=4, H=8, N=2048, D=64] fp32.

constexpr int TPB  = 256;
constexpr int MQ   = 16;      // queries per CTA
constexpr int TK   = 256;     // keys per SMEM tile
constexpr int D    = 64;
constexpr int N    = 2048;
constexpr int NT   = N / TK;  // 8
constexpr int BH   = 32;

constexpr int LSTR = 2056;    // fp32 logits row stride (pad 8)
constexpr int KSTR = 72;      // bf16 tile row stride (64 + 8 pad) -> 144 B/row
constexpr int QSTR = 68;      // fp32 Q staging row stride

// SMEM float offsets
constexpr int OFF_LOGITS = 0;
constexpr int OFF_QBUF   = OFF_LOGITS + MQ * LSTR;        // 32896
constexpr int OFF_INV2S  = OFF_QBUF + MQ * QSTR;          // +1088
constexpr int OFF_TILEHI = ((OFF_INV2S + MQ + 15) / 16) * 16;   // 16B aligned
constexpr int TILE_WORDS = TK * (KSTR / 2);               // u32 words = 9216
constexpr int OFF_TILELO = OFF_TILEHI + TILE_WORDS;
constexpr int SMEM_FLOATS = OFF_TILELO + TILE_WORDS;
constexpr int PSTR = 72;                                  // pbuf fp32 row stride

// ---------------- PTX helpers ----------------
__device__ __forceinline__ uint32_t pack_bf16x2(float lo, float hi) {
    uint32_t r;
    asm("cvt.rn.bf16x2.f32 %0, %1, %2;" : "=r"(r) : "f"(hi), "f"(lo));
    return r;
}
// split (x,y) fp32 pair into bf16 hi-pair and exact-residual lo-pair
__device__ __forceinline__ void split2(float x, float y, uint32_t& h, uint32_t& l) {
    h = pack_bf16x2(x, y);
    float xh = __uint_as_float(h << 16);
    float yh = __uint_as_float(h & 0xffff0000u);
    l = pack_bf16x2(x - xh, y - yh);
}
__device__ __forceinline__ void mma16816(float c[4], const uint32_t a[4],
                                         uint32_t b0, uint32_t b1) {
    asm volatile(
        "mma.sync.aligned.m16n8k16.row.col.f32.bf16.bf16.f32 "
        "{%0,%1,%2,%3}, {%4,%5,%6,%7}, {%8,%9}, {%0,%1,%2,%3};"
        : "+f"(c[0]), "+f"(c[1]), "+f"(c[2]), "+f"(c[3])
        : "r"(a[0]), "r"(a[1]), "r"(a[2]), "r"(a[3]), "r"(b0), "r"(b1));
}
__device__ __forceinline__ void ldmx4(uint32_t r[4], uint32_t addr) {
    asm volatile("ldmatrix.sync.aligned.m8n8.x4.shared.b16 {%0,%1,%2,%3}, [%4];"
                 : "=r"(r[0]), "=r"(r[1]), "=r"(r[2]), "=r"(r[3]) : "r"(addr));
}
__device__ __forceinline__ void ldmx4_t(uint32_t r[4], uint32_t addr) {
    asm volatile("ldmatrix.sync.aligned.m8n8.x4.trans.shared.b16 {%0,%1,%2,%3}, [%4];"
                 : "=r"(r[0]), "=r"(r[1]), "=r"(r[2]), "=r"(r[3]) : "r"(addr));
}

// Load a TKxD fp32 tile (row-major [k][d]) -> bf16 hi/lo tiles [k][KSTR]
__device__ __forceinline__ void load_tile(const float* __restrict__ src,
                                          uint32_t* __restrict__ hiW,
                                          uint32_t* __restrict__ loW, int tid)
{
#pragma unroll
    for (int r = 0; r < 16; r++) {
        int idx = r * 256 + tid;
        int kk  = idx >> 4;            // key row 0..255
        int d4  = (idx & 15) << 2;     // 0,4,...,60
        float4 v = *reinterpret_cast<const float4*>(src + kk * D + d4);
        uint32_t h01, l01, h23, l23;
        split2(v.x, v.y, h01, l01);
        split2(v.z, v.w, h23, l23);
        int w = kk * (KSTR / 2) + (d4 >> 1);
        hiW[w] = h01; hiW[w + 1] = h23;
        loW[w] = l01; loW[w + 1] = l23;
    }
}

__global__ __launch_bounds__(TPB, 1)
void stk_branch_kernel(const float* __restrict__ Q, const float* __restrict__ K,
                       const float* __restrict__ V, const float* __restrict__ scale_p,
                       float* __restrict__ O)
{
    extern __shared__ float sm[];
    float*    logits = sm + OFF_LOGITS;
    float*    qbuf   = sm + OFF_QBUF;
    float*    inv2s  = sm + OFF_INV2S;
    uint32_t* tileHi = reinterpret_cast<uint32_t*>(sm + OFF_TILEHI);
    uint32_t* tileLo = reinterpret_cast<uint32_t*>(sm + OFF_TILELO);

    const int tid  = threadIdx.x;
    const int wid  = tid >> 5, lane = tid & 31;
    const int gid  = lane >> 2, tg = lane & 3;
    const int lg   = lane >> 3, lr = lane & 7;

    const int bh    = blockIdx.y;
    const int qbase = blockIdx.x * MQ;
    const int base  = bh * (N * D);
    const float sc  = __ldg(scale_p);

    const uint32_t smemB = (uint32_t)__cvta_generic_to_shared(sm);
    const uint32_t hiB   = smemB + OFF_TILEHI * 4;
    const uint32_t loB   = smemB + OFF_TILELO * 4;

    // ---- Stage Q fp32 into smem ----
    {
        int o4 = tid << 2;
        int qq = o4 >> 6, dd = o4 & 63;
        float4 qv = *reinterpret_cast<const float4*>(Q + base + (qbase + qq) * D + dd);
        *reinterpret_cast<float4*>(&qbuf[qq * QSTR + dd]) = qv;
    }
    __syncthreads();

    // ---- Build Q A-fragments (hi/lo) in registers: 4 k-steps ----
    uint32_t aQh[4][4], aQl[4][4];
#pragma unroll
    for (int ks = 0; ks < 4; ks++) {
        int c0 = ks * 16 + 2 * tg;
        float2 v00 = *reinterpret_cast<const float2*>(&qbuf[gid * QSTR + c0]);
        float2 v10 = *reinterpret_cast<const float2*>(&qbuf[(gid + 8) * QSTR + c0]);
        float2 v01 = *reinterpret_cast<const float2*>(&qbuf[gid * QSTR + c0 + 8]);
        float2 v11 = *reinterpret_cast<const float2*>(&qbuf[(gid + 8) * QSTR + c0 + 8]);
        split2(v00.x, v00.y, aQh[ks][0], aQl[ks][0]);
        split2(v10.x, v10.y, aQh[ks][1], aQl[ks][1]);
        split2(v01.x, v01.y, aQh[ks][2], aQl[ks][2]);
        split2(v11.x, v11.y, aQh[ks][3], aQl[ks][3]);
    }

    // ---- Phase 1: logits = sc * Q K^T (tensor cores, 3x bf16 split) ----
    for (int t = 0; t < NT; t++) {
        __syncthreads();
        load_tile(K + base + t * TK * D, tileHi, tileLo, tid);
        __syncthreads();

        int ns = wid * 32;
#pragma unroll
        for (int j = 0; j < 2; j++) {
            int np = ns + j * 16;
            float c0[4] = {0.f, 0.f, 0.f, 0.f};
            float c1[4] = {0.f, 0.f, 0.f, 0.f};
            // no-trans ldmatrix: row = key, col = d
            uint32_t rowv = np + lr + ((lg >= 2) ? 8 : 0);
#pragma unroll
            for (int ks = 0; ks < 4; ks++) {
                uint32_t colv = ks * 16 + ((lg & 1) ? 8 : 0);
                uint32_t off  = rowv * (KSTR * 2) + colv * 2;
                uint32_t bhr[4], blr[4];
                ldmx4(bhr, hiB + off);
                ldmx4(blr, loB + off);
                mma16816(c0, aQh[ks], bhr[0], bhr[1]);
                mma16816(c0, aQh[ks], blr[0], blr[1]);
                mma16816(c0, aQl[ks], bhr[0], bhr[1]);
                mma16816(c1, aQh[ks], bhr[2], bhr[3]);
                mma16816(c1, aQh[ks], blr[2], blr[3]);
                mma16816(c1, aQl[ks], bhr[2], bhr[3]);
            }
            int nb = t * TK + np;
            *reinterpret_cast<float2*>(&logits[gid * LSTR + nb + 2 * tg]) =
                make_float2(c0[0] * sc, c0[1] * sc);
            *reinterpret_cast<float2*>(&logits[(gid + 8) * LSTR + nb + 2 * tg]) =
                make_float2(c0[2] * sc, c0[3] * sc);
            *reinterpret_cast<float2*>(&logits[gid * LSTR + nb + 8 + 2 * tg]) =
                make_float2(c1[0] * sc, c1[1] * sc);
            *reinterpret_cast<float2*>(&logits[(gid + 8) * LSTR + nb + 8 + 2 * tg]) =
                make_float2(c1[2] * sc, c1[3] * sc);
        }
    }
    __syncthreads();

    // ---- Phase 2: per-row double softmax in place (warp w owns rows 2w, 2w+1) ----
    {
#pragma unroll
        for (int rr = 0; rr < 2; rr++) {
            float* L = logits + ((wid << 1) + rr) * LSTR;

            float m = -1e30f;
            for (int it = 0; it < 16; it++) {
                float4 x = *reinterpret_cast<const float4*>(&L[(it * 32 + lane) << 2]);
                m = fmaxf(m, fmaxf(fmaxf(x.x, x.y), fmaxf(x.z, x.w)));
            }
#pragma unroll
            for (int o = 16; o; o >>= 1) m = fmaxf(m, __shfl_xor_sync(0xffffffffu, m, o));

            float s = 0.f;
            for (int it = 0; it < 16; it++) {
                float4 x = *reinterpret_cast<const float4*>(&L[(it * 32 + lane) << 2]);
                s += __expf(2.f * (x.x - m)) + __expf(2.f * (x.y - m))
                   + __expf(2.f * (x.z - m)) + __expf(2.f * (x.w - m));
            }
#pragma unroll
            for (int o = 16; o; o >>= 1) s += __shfl_xor_sync(0xffffffffu, s, o);
            float inv1 = 1.f / s;

            float m2 = -1e30f;
            for (int it = 0; it < 16; it++) {
                float4* p4 = reinterpret_cast<float4*>(&L[(it * 32 + lane) << 2]);
                float4 x = *p4;
                x.x = x.x * (__expf(2.f * (x.x - m)) * inv1);
                x.y = x.y * (__expf(2.f * (x.y - m)) * inv1);
                x.z = x.z * (__expf(2.f * (x.z - m)) * inv1);
                x.w = x.w * (__expf(2.f * (x.w - m)) * inv1);
                *p4 = x;
                m2 = fmaxf(m2, fmaxf(fmaxf(x.x, x.y), fmaxf(x.z, x.w)));
            }
#pragma unroll
            for (int o = 16; o; o >>= 1) m2 = fmaxf(m2, __shfl_xor_sync(0xffffffffu, m2, o));

            float s2 = 0.f;
            for (int it = 0; it < 16; it++) {
                float4* p4 = reinterpret_cast<float4*>(&L[(it * 32 + lane) << 2]);
                float4 x = *p4;
                x.x = __expf(x.x - m2); x.y = __expf(x.y - m2);
                x.z = __expf(x.z - m2); x.w = __expf(x.w - m2);
                *p4 = x;
                s2 += x.x + x.y + x.z + x.w;
            }
#pragma unroll
            for (int o = 16; o; o >>= 1) s2 += __shfl_xor_sync(0xffffffffu, s2, o);
            if (lane == 0) inv2s[(wid << 1) + rr] = 1.f / s2;
        }
    }

    // ---- Phase 3: O = P V (tensor cores, warp-split over keys) ----
    float oc[8][4];
#pragma unroll
    for (int j = 0; j < 8; j++)
#pragma unroll
        for (int i = 0; i < 4; i++) oc[j][i] = 0.f;

    for (int t = 0; t < NT; t++) {
        __syncthreads();
        load_tile(V + base + t * TK * D, tileHi, tileLo, tid);
        __syncthreads();

        int kb = wid * 32;
#pragma unroll
        for (int ks2 = 0; ks2 < 2; ks2++) {
            int kloc = kb + ks2 * 16;
            int kg   = t * TK + kloc;
            float2 p00 = *reinterpret_cast<const float2*>(&logits[gid * LSTR + kg + 2 * tg]);
            float2 p10 = *reinterpret_cast<const float2*>(&logits[(gid + 8) * LSTR + kg + 2 * tg]);
            float2 p01 = *reinterpret_cast<const float2*>(&logits[gid * LSTR + kg + 8 + 2 * tg]);
            float2 p11 = *reinterpret_cast<const float2*>(&logits[(gid + 8) * LSTR + kg + 8 + 2 * tg]);
            uint32_t ah[4], al[4];
            split2(p00.x, p00.y, ah[0], al[0]);
            split2(p10.x, p10.y, ah[1], al[1]);
            split2(p01.x, p01.y, ah[2], al[2]);
            split2(p11.x, p11.y, ah[3], al[3]);

            // trans ldmatrix: tiles (b0: k rows, b1: k+8 rows) x (d, d+8)
            uint32_t rowv = kloc + lr + ((lg & 1) ? 8 : 0);
#pragma unroll
            for (int j = 0; j < 4; j++) {
                uint32_t colv = j * 16 + ((lg >= 2) ? 8 : 0);
                uint32_t off  = rowv * (KSTR * 2) + colv * 2;
                uint32_t bhr[4], blr[4];
                ldmx4_t(bhr, hiB + off);
                ldmx4_t(blr, loB + off);
                mma16816(oc[2 * j],     ah, bhr[0], bhr[1]);
                mma16816(oc[2 * j],     ah, blr[0], blr[1]);
                mma16816(oc[2 * j],     al, bhr[0], bhr[1]);
                mma16816(oc[2 * j + 1], ah, bhr[2], bhr[3]);
                mma16816(oc[2 * j + 1], ah, blr[2], blr[3]);
                mma16816(oc[2 * j + 1], al, bhr[2], bhr[3]);
            }
        }
    }

    // ---- Cross-warp reduction of partial O (reuse tile buffer) ----
    __syncthreads();
    float* pbuf = reinterpret_cast<float*>(tileHi);
#pragma unroll
    for (int dt = 0; dt < 8; dt++) {
        *reinterpret_cast<float2*>(&pbuf[wid * (MQ * PSTR) + gid * PSTR + dt * 8 + 2 * tg]) =
            make_float2(oc[dt][0], oc[dt][1]);
        *reinterpret_cast<float2*>(&pbuf[wid * (MQ * PSTR) + (gid + 8) * PSTR + dt * 8 + 2 * tg]) =
            make_float2(oc[dt][2], oc[dt][3]);
    }
    __syncthreads();

    {
        int o4 = tid << 2;
        int qq = o4 >> 6, dd = o4 & 63;
        float r0 = 0.f, r1 = 0.f, r2 = 0.f, r3 = 0.f;
#pragma unroll
        for (int w = 0; w < 8; w++) {
            const float* p = &pbuf[w * (MQ * PSTR) + qq * PSTR + dd];
            r0 += p[0]; r1 += p[1]; r2 += p[2]; r3 += p[3];
        }
        float iv = inv2s[qq];
        *reinterpret_cast<float4*>(O + base + (qbase + qq) * D + dd) =
            make_float4(r0 * iv, r1 * iv, r2 * iv, r3 * iv);
    }
}

extern "C" void kernel_launch(void* const* d_in, const int* in_sizes, int n_in,
                              void* d_out, int out_size)
{
    const float* q  = (const float*)d_in[0];
    const float* k  = (const float*)d_in[1];
    const float* v  = (const float*)d_in[2];
    const float* sc = (const float*)d_in[3];
    float* o = (float*)d_out;

    size_t smem = (size_t)SMEM_FLOATS * sizeof(float);
    cudaFuncSetAttribute(stk_branch_kernel,
                         cudaFuncAttributeMaxDynamicSharedMemorySize, (int)smem);
    dim3 grid(N / MQ, BH);
    stk_branch_kernel<<<grid, TPB, smem>>>(q, k, v, sc, o);
}